// round 4
// baseline (speedup 1.0000x reference)
#include <cuda_runtime.h>

#define D 64
#define MAXN 100000
#define MAXE 1600000
#define NLAYERS 3
#define BN_EPS 1e-5f

// ---------------- scratch (device globals; no allocation allowed) ----------------
__device__ float g_tsc[MAXN * D];        // dinv[n] * (h[n] @ W)
__device__ float g_y[MAXN * D];          // pre-BN layer output
__device__ float g_dinv[MAXN];
__device__ int   g_deg[MAXN];
__device__ int   g_rowptr[MAXN + 1];
__device__ int   g_cnt[MAXN];
__device__ int   g_csrc[MAXE];
__device__ float g_stats[NLAYERS * 2 * D];   // per layer: [64 sums][64 sumsqs]
__device__ float g_psum[128 * D];
__device__ int   g_pcnt[128];
__device__ int   g_bsums[1024];

// ---------------- graph preprocessing ----------------
__global__ void k_degree(const int* __restrict__ ei, int E) {
    int e = blockIdx.x * blockDim.x + threadIdx.x;
    if (e < E) atomicAdd(&g_deg[ei[E + e]], 1);
}

__global__ void k_dinv(int N) {
    int n = blockIdx.x * blockDim.x + threadIdx.x;
    if (n < N) g_dinv[n] = rsqrtf((float)(g_deg[n] + 1));  // +1 self loop
}

// block-wise exclusive scan of g_deg -> g_rowptr (partial), block totals -> g_bsums
__global__ void k_scan1(int N) {
    __shared__ int s[1024];
    int t = threadIdx.x;
    int i = blockIdx.x * 1024 + t;
    int v = (i < N) ? g_deg[i] : 0;
    s[t] = v;
    __syncthreads();
    for (int off = 1; off < 1024; off <<= 1) {
        int x = (t >= off) ? s[t - off] : 0;
        __syncthreads();
        s[t] += x;
        __syncthreads();
    }
    if (i < N) g_rowptr[i] = s[t] - v;      // exclusive
    if (t == 1023) g_bsums[blockIdx.x] = s[t];
}

__global__ void k_scan2(int nb) {
    __shared__ int s[1024];
    int t = threadIdx.x;
    int v = (t < nb) ? g_bsums[t] : 0;
    s[t] = v;
    __syncthreads();
    for (int off = 1; off < 1024; off <<= 1) {
        int x = (t >= off) ? s[t - off] : 0;
        __syncthreads();
        s[t] += x;
        __syncthreads();
    }
    if (t < nb) g_bsums[t] = s[t] - v;      // exclusive block offsets
}

__global__ void k_scan3(int N, int E) {
    int i = blockIdx.x * blockDim.x + threadIdx.x;
    if (i < N) {
        int r = g_rowptr[i] + g_bsums[i >> 10];
        g_rowptr[i] = r;
        g_cnt[i] = r;   // fill cursor
    }
    if (i == 0) g_rowptr[N] = E;
}

__global__ void k_fill(const int* __restrict__ ei, int E) {
    int e = blockIdx.x * blockDim.x + threadIdx.x;
    if (e < E) {
        int s = ei[e];
        int d = ei[E + e];
        int p = atomicAdd(&g_cnt[d], 1);
        g_csrc[p] = s;
    }
}

// ---------------- dense transform: t_scaled = dinv * (act(A) @ W) ----------------
// act = identity for layer 0, BN(prev stats)+ReLU otherwise (fused here).
// Block: 512 threads = 32 rows x 16 col-groups (float4 of output columns).
__global__ void __launch_bounds__(512) k_transform(
    const float* __restrict__ A, const float* __restrict__ W,
    const float* __restrict__ gammas, const float* __restrict__ betas,
    int layer, int N, int apply_bn)
{
    __shared__ float4 Ws4[64 * 16];     // W[k][c] as float4 groups
    __shared__ float hs[32 * 68];       // padded input tile
    __shared__ float sc[64], sh[64];    // BN scale/shift
    __shared__ float dl[32];

    int tid = threadIdx.x;
    int row = tid >> 4;
    int cg  = tid & 15;

    if (tid < 64) {
        if (apply_bn) {
            float invN = 1.0f / (float)N;
            int   pl   = layer - 1;
            float mean = g_stats[pl * 128 + tid] * invN;
            float var  = g_stats[pl * 128 + 64 + tid] * invN - mean * mean;
            float s    = gammas[pl * 64 + tid] * rsqrtf(var + BN_EPS);
            sc[tid] = s;
            sh[tid] = betas[pl * 64 + tid] - mean * s;
        } else {
            sc[tid] = 1.0f;
            sh[tid] = 0.0f;
        }
    }

    // load W (independent of BN params)
    const float4* W4 = (const float4*)W;
    Ws4[tid]       = W4[tid];
    Ws4[tid + 512] = W4[tid + 512];

    int n = blockIdx.x * 32 + row;
    float4 hv = make_float4(0.f, 0.f, 0.f, 0.f);
    if (n < N) hv = ((const float4*)A)[n * 16 + cg];
    if (cg == 0) dl[row] = (n < N) ? g_dinv[n] : 0.f;
    __syncthreads();

    if (apply_bn) {
        int c = cg * 4;
        hv.x = fmaxf(fmaf(hv.x, sc[c + 0], sh[c + 0]), 0.f);
        hv.y = fmaxf(fmaf(hv.y, sc[c + 1], sh[c + 1]), 0.f);
        hv.z = fmaxf(fmaf(hv.z, sc[c + 2], sh[c + 2]), 0.f);
        hv.w = fmaxf(fmaf(hv.w, sc[c + 3], sh[c + 3]), 0.f);
    }
    *(float4*)&hs[row * 68 + cg * 4] = hv;
    __syncthreads();

    float4 acc = make_float4(0.f, 0.f, 0.f, 0.f);
#pragma unroll
    for (int k = 0; k < 64; k += 4) {
        float4 h4 = *(const float4*)&hs[row * 68 + k];
        float4 w0 = Ws4[(k + 0) * 16 + cg];
        float4 w1 = Ws4[(k + 1) * 16 + cg];
        float4 w2 = Ws4[(k + 2) * 16 + cg];
        float4 w3 = Ws4[(k + 3) * 16 + cg];
        acc.x = fmaf(h4.x, w0.x, acc.x); acc.y = fmaf(h4.x, w0.y, acc.y);
        acc.z = fmaf(h4.x, w0.z, acc.z); acc.w = fmaf(h4.x, w0.w, acc.w);
        acc.x = fmaf(h4.y, w1.x, acc.x); acc.y = fmaf(h4.y, w1.y, acc.y);
        acc.z = fmaf(h4.y, w1.z, acc.z); acc.w = fmaf(h4.y, w1.w, acc.w);
        acc.x = fmaf(h4.z, w2.x, acc.x); acc.y = fmaf(h4.z, w2.y, acc.y);
        acc.z = fmaf(h4.z, w2.z, acc.z); acc.w = fmaf(h4.z, w2.w, acc.w);
        acc.x = fmaf(h4.w, w3.x, acc.x); acc.y = fmaf(h4.w, w3.y, acc.y);
        acc.z = fmaf(h4.w, w3.z, acc.z); acc.w = fmaf(h4.w, w3.w, acc.w);
    }

    if (n < N) {
        float dv = dl[row];
        float4 o = make_float4(acc.x * dv, acc.y * dv, acc.z * dv, acc.w * dv);
        ((float4*)g_tsc)[n * 16 + cg] = o;
    }
}

// ---------------- CSR gather-aggregate + fused BN stats ----------------
// warp per node; lane holds feature pair (2*lane, 2*lane+1).
__global__ void __launch_bounds__(256) k_gather(int layer, int N)
{
    __shared__ float ssum[64], ssq[64];
    int tid  = threadIdx.x;
    int lane = tid & 31;
    int wid  = tid >> 5;
    if (tid < 64) { ssum[tid] = 0.f; ssq[tid] = 0.f; }
    __syncthreads();

    float2 lsum = make_float2(0.f, 0.f);
    float2 lsq  = make_float2(0.f, 0.f);

    const float2* base = (const float2*)g_tsc;
    int warps = gridDim.x * 8;
    for (int n = blockIdx.x * 8 + wid; n < N; n += warps) {
        int s0 = g_rowptr[n];
        int s1 = g_rowptr[n + 1];
        float2 acc = base[n * 32 + lane];   // self loop term
        int e = s0;
        for (; e + 4 <= s1; e += 4) {
            int a = g_csrc[e + 0];
            int b = g_csrc[e + 1];
            int c = g_csrc[e + 2];
            int d = g_csrc[e + 3];
            float2 v0 = base[a * 32 + lane];
            float2 v1 = base[b * 32 + lane];
            float2 v2 = base[c * 32 + lane];
            float2 v3 = base[d * 32 + lane];
            acc.x += (v0.x + v1.x) + (v2.x + v3.x);
            acc.y += (v0.y + v1.y) + (v2.y + v3.y);
        }
        for (; e < s1; ++e) {
            int a = g_csrc[e];
            float2 v = base[a * 32 + lane];
            acc.x += v.x; acc.y += v.y;
        }
        float dv = g_dinv[n];
        float2 yv = make_float2(acc.x * dv, acc.y * dv);
        ((float2*)g_y)[n * 32 + lane] = yv;
        lsum.x += yv.x; lsum.y += yv.y;
        lsq.x  += yv.x * yv.x; lsq.y += yv.y * yv.y;
    }

    atomicAdd(&ssum[lane * 2 + 0], lsum.x);
    atomicAdd(&ssum[lane * 2 + 1], lsum.y);
    atomicAdd(&ssq[lane * 2 + 0], lsq.x);
    atomicAdd(&ssq[lane * 2 + 1], lsq.y);
    __syncthreads();
    if (tid < 64) {
        atomicAdd(&g_stats[layer * 128 + tid], ssum[tid]);
        atomicAdd(&g_stats[layer * 128 + 64 + tid], ssq[tid]);
    }
}

// ---------------- pooling: BN+ReLU fused, segment-sum by graph ----------------
__global__ void k_pool(const int* __restrict__ batch,
                       const float* __restrict__ gammas,
                       const float* __restrict__ betas,
                       int layer, int N)
{
    __shared__ float sc[64], sh[64];
    if (threadIdx.x < 64) {
        float invN = 1.0f / (float)N;
        float mean = g_stats[layer * 128 + threadIdx.x] * invN;
        float var  = g_stats[layer * 128 + 64 + threadIdx.x] * invN - mean * mean;
        float s    = gammas[layer * 64 + threadIdx.x] * rsqrtf(var + BN_EPS);
        sc[threadIdx.x] = s;
        sh[threadIdx.x] = betas[layer * 64 + threadIdx.x] - mean * s;
    }
    __syncthreads();

    int t = blockIdx.x * blockDim.x + threadIdx.x;
    int n = t >> 2;
    int q = t & 3;
    if (n >= N) return;
    int g = batch[n];
#pragma unroll
    for (int j = 0; j < 4; j++) {
        int c0 = q * 16 + j * 4;
        float4 v = ((const float4*)g_y)[n * 16 + q * 4 + j];
        v.x = fmaxf(fmaf(v.x, sc[c0 + 0], sh[c0 + 0]), 0.f);
        v.y = fmaxf(fmaf(v.y, sc[c0 + 1], sh[c0 + 1]), 0.f);
        v.z = fmaxf(fmaf(v.z, sc[c0 + 2], sh[c0 + 2]), 0.f);
        v.w = fmaxf(fmaf(v.w, sc[c0 + 3], sh[c0 + 3]), 0.f);
        atomicAdd(&g_psum[g * 64 + c0 + 0], v.x);
        atomicAdd(&g_psum[g * 64 + c0 + 1], v.y);
        atomicAdd(&g_psum[g * 64 + c0 + 2], v.z);
        atomicAdd(&g_psum[g * 64 + c0 + 3], v.w);
    }
    if (q == 0) atomicAdd(&g_pcnt[g], 1);
}

__global__ void k_div(int G, float* __restrict__ out)
{
    int t = blockIdx.x * blockDim.x + threadIdx.x;
    if (t < G * 64) {
        float c = (float)g_pcnt[t >> 6];
        out[t] = g_psum[t] / fmaxf(c, 1.0f);
    }
}

// ---------------- launch ----------------
extern "C" void kernel_launch(void* const* d_in, const int* in_sizes, int n_in,
                              void* d_out, int out_size)
{
    const float* x      = (const float*)d_in[0];
    const int*   ei     = (const int*)d_in[1];     // int32: JAX x64 disabled
    const int*   batch  = (const int*)d_in[2];     // int32
    const float* Ws     = (const float*)d_in[3];
    // d_in[4] = bs: cancels exactly through BatchNorm (uniform shift), skipped.
    const float* gammas = (const float*)d_in[5];
    const float* betas  = (const float*)d_in[6];

    int N = in_sizes[0] / 64;
    int E = in_sizes[1] / 2;
    int G = out_size / 64;

    void *p_deg, *p_stats, *p_psum, *p_pcnt, *p_y;
    cudaGetSymbolAddress(&p_deg, g_deg);
    cudaGetSymbolAddress(&p_stats, g_stats);
    cudaGetSymbolAddress(&p_psum, g_psum);
    cudaGetSymbolAddress(&p_pcnt, g_pcnt);
    cudaGetSymbolAddress(&p_y, g_y);

    cudaMemsetAsync(p_deg, 0, (size_t)N * sizeof(int));
    cudaMemsetAsync(p_stats, 0, NLAYERS * 128 * sizeof(float));
    cudaMemsetAsync(p_psum, 0, (size_t)G * 64 * sizeof(float));
    cudaMemsetAsync(p_pcnt, 0, (size_t)G * sizeof(int));

    const int tb = 256;
    k_degree<<<(E + tb - 1) / tb, tb>>>(ei, E);
    k_dinv<<<(N + tb - 1) / tb, tb>>>(N);

    int nb = (N + 1023) / 1024;
    k_scan1<<<nb, 1024>>>(N);
    k_scan2<<<1, 1024>>>(nb);
    k_scan3<<<(N + tb - 1) / tb, tb>>>(N, E);
    k_fill<<<(E + tb - 1) / tb, tb>>>(ei, E);

    for (int l = 0; l < NLAYERS; ++l) {
        const float* A = (l == 0) ? x : (const float*)p_y;
        k_transform<<<(N + 31) / 32, 512>>>(A, Ws + (size_t)l * 64 * 64,
                                            gammas, betas, l, N, (l > 0) ? 1 : 0);
        k_gather<<<1184, 256>>>(l, N);
    }

    k_pool<<<(N * 4 + tb - 1) / tb, tb>>>(batch, gammas, betas, NLAYERS - 1, N);
    k_div<<<(G * 64 + tb - 1) / tb, tb>>>(G, (float*)d_out);
}

// round 8
// speedup vs baseline: 1.7054x; 1.7054x over previous
#include <cuda_runtime.h>
#include <cuda_fp16.h>

#define D 64
#define MAXN 100000
#define MAXE 1600000
#define NLAYERS 3
#define BN_EPS 1e-5f

// ---------------- scratch (device globals; no allocation allowed) ----------------
__device__ __half g_tsch[MAXN * D];      // fp16: dinv[n] * (h[n] @ W)
__device__ float  g_y[MAXN * D];         // pre-BN layer output (fp32)
__device__ float  g_dinv[MAXN];
__device__ int    g_deg[MAXN];
__device__ int    g_rowptr[MAXN + 1];
__device__ int    g_cnt[MAXN];
__device__ int    g_csrc[MAXE];
__device__ float  g_stats[NLAYERS * 2 * D];  // per layer: [64 sums][64 sumsqs]
__device__ float  g_psum[128 * D];
__device__ int    g_pcnt[128];
__device__ int    g_bsums[1024];

__device__ __forceinline__ void fma4(float4& a, float h, const float4& w) {
    a.x = fmaf(h, w.x, a.x);
    a.y = fmaf(h, w.y, a.y);
    a.z = fmaf(h, w.z, a.z);
    a.w = fmaf(h, w.w, a.w);
}

// ---------------- graph preprocessing ----------------
__global__ void k_degree(const int* __restrict__ ei, int E) {
    int e = blockIdx.x * blockDim.x + threadIdx.x;
    if (e < E) atomicAdd(&g_deg[ei[E + e]], 1);
}

// block-wise exclusive scan of g_deg -> g_rowptr (partial), block totals -> g_bsums
__global__ void k_scan1(int N) {
    __shared__ int s[1024];
    int t = threadIdx.x;
    int i = blockIdx.x * 1024 + t;
    int v = (i < N) ? g_deg[i] : 0;
    s[t] = v;
    __syncthreads();
    for (int off = 1; off < 1024; off <<= 1) {
        int x = (t >= off) ? s[t - off] : 0;
        __syncthreads();
        s[t] += x;
        __syncthreads();
    }
    if (i < N) g_rowptr[i] = s[t] - v;      // exclusive
    if (t == 1023) g_bsums[blockIdx.x] = s[t];
}

__global__ void k_scan2(int nb) {
    __shared__ int s[1024];
    int t = threadIdx.x;
    int v = (t < nb) ? g_bsums[t] : 0;
    s[t] = v;
    __syncthreads();
    for (int off = 1; off < 1024; off <<= 1) {
        int x = (t >= off) ? s[t - off] : 0;
        __syncthreads();
        s[t] += x;
        __syncthreads();
    }
    if (t < nb) g_bsums[t] = s[t] - v;      // exclusive block offsets
}

__global__ void k_scan3(int N, int E) {
    int i = blockIdx.x * blockDim.x + threadIdx.x;
    if (i < N) {
        int r = g_rowptr[i] + g_bsums[i >> 10];
        g_rowptr[i] = r;
        g_cnt[i] = r;                              // fill cursor
        g_dinv[i] = rsqrtf((float)(g_deg[i] + 1)); // +1 self loop (fused k_dinv)
    }
    if (i == 0) g_rowptr[N] = E;
}

__global__ void k_fill(const int* __restrict__ ei, int E) {
    int e = blockIdx.x * blockDim.x + threadIdx.x;
    if (e < E) {
        int s = ei[e];
        int d = ei[E + e];
        int p = atomicAdd(&g_cnt[d], 1);
        g_csrc[p] = s;
    }
}

// ---------------- dense transform: t_scaled = dinv * (act(A) @ W) -> fp16 ----------
// act = identity for layer 0, BN(prev stats)+ReLU otherwise (fused at tile load).
// 128 threads cover 128 rows x 64 cols; thread = 4 rows x 16 cols register tile.
__global__ void __launch_bounds__(128) k_transform(
    const float* __restrict__ A, const float* __restrict__ W,
    const float* __restrict__ gammas, const float* __restrict__ betas,
    int layer, int N, int apply_bn)
{
    __shared__ float Ws[64 * 64];    // W[k][c], 16KB
    __shared__ float hs[128 * 68];   // padded input tile, 34KB
    __shared__ float sc[64], sh[64];
    __shared__ float dl[128];

    int tid  = threadIdx.x;
    int rg   = tid >> 2;   // 0..31 -> rows rg*4 .. rg*4+3
    int cg   = tid & 3;    // 0..3  -> cols cg*16 .. cg*16+15
    int row0 = blockIdx.x * 128;

    if (tid < 64) {
        if (apply_bn) {
            float invN = 1.0f / (float)N;
            int   pl   = layer - 1;
            float mean = g_stats[pl * 128 + tid] * invN;
            float var  = g_stats[pl * 128 + 64 + tid] * invN - mean * mean;
            float s    = gammas[pl * 64 + tid] * rsqrtf(var + BN_EPS);
            sc[tid] = s;
            sh[tid] = betas[pl * 64 + tid] - mean * s;
        } else {
            sc[tid] = 1.0f;
            sh[tid] = 0.0f;
        }
    }
    // load W to smem: 1024 float4, 8 per thread
    {
        const float4* W4  = (const float4*)W;
        float4*       Ws4 = (float4*)Ws;
#pragma unroll
        for (int i = 0; i < 8; i++) Ws4[tid + i * 128] = W4[tid + i * 128];
    }
    {
        int n = row0 + tid;
        dl[tid] = (n < N) ? g_dinv[n] : 0.f;
    }
    __syncthreads();   // sc/sh ready for BN-at-load

    // load h tile (BN+ReLU fused), 2048 float4 / 128 threads = 16 each
#pragma unroll
    for (int i = 0; i < 16; i++) {
        int idx = tid + i * 128;
        int r   = idx >> 4;
        int c4  = idx & 15;
        int n   = row0 + r;
        float4 hv = make_float4(0.f, 0.f, 0.f, 0.f);
        if (n < N) hv = ((const float4*)A)[n * 16 + c4];
        if (apply_bn) {
            int c = c4 * 4;
            hv.x = fmaxf(fmaf(hv.x, sc[c + 0], sh[c + 0]), 0.f);
            hv.y = fmaxf(fmaf(hv.y, sc[c + 1], sh[c + 1]), 0.f);
            hv.z = fmaxf(fmaf(hv.z, sc[c + 2], sh[c + 2]), 0.f);
            hv.w = fmaxf(fmaf(hv.w, sc[c + 3], sh[c + 3]), 0.f);
        }
        *(float4*)&hs[r * 68 + c4 * 4] = hv;
    }
    __syncthreads();

    float4 acc[4][4];
#pragma unroll
    for (int i = 0; i < 4; i++)
#pragma unroll
        for (int j = 0; j < 4; j++)
            acc[i][j] = make_float4(0.f, 0.f, 0.f, 0.f);

    const float* hrow = &hs[(rg * 4) * 68];
#pragma unroll 8
    for (int k = 0; k < 64; k++) {
        float h0 = hrow[k];
        float h1 = hrow[68 + k];
        float h2 = hrow[136 + k];
        float h3 = hrow[204 + k];
        const float4* wrow = (const float4*)&Ws[k * 64 + cg * 16];
        float4 w0 = wrow[0], w1 = wrow[1], w2 = wrow[2], w3 = wrow[3];
        fma4(acc[0][0], h0, w0); fma4(acc[0][1], h0, w1); fma4(acc[0][2], h0, w2); fma4(acc[0][3], h0, w3);
        fma4(acc[1][0], h1, w0); fma4(acc[1][1], h1, w1); fma4(acc[1][2], h1, w2); fma4(acc[1][3], h1, w3);
        fma4(acc[2][0], h2, w0); fma4(acc[2][1], h2, w1); fma4(acc[2][2], h2, w2); fma4(acc[2][3], h2, w3);
        fma4(acc[3][0], h3, w0); fma4(acc[3][1], h3, w1); fma4(acc[3][2], h3, w2); fma4(acc[3][3], h3, w3);
    }

    // scale by dinv, convert to fp16, store 32B per row (2x uint4)
#pragma unroll
    for (int i = 0; i < 4; i++) {
        int n = row0 + rg * 4 + i;
        if (n < N) {
            float dv = dl[rg * 4 + i];
            __half2 o[8];
#pragma unroll
            for (int j = 0; j < 4; j++) {
                float4 a = acc[i][j];
                o[j * 2 + 0] = __floats2half2_rn(a.x * dv, a.y * dv);
                o[j * 2 + 1] = __floats2half2_rn(a.z * dv, a.w * dv);
            }
            uint4* dst = (uint4*)&g_tsch[n * 64 + cg * 16];
            dst[0] = *(uint4*)&o[0];
            dst[1] = *(uint4*)&o[4];
        }
    }
}

// ---------------- CSR gather-aggregate (fp16 msgs) + fused BN stats ----------------
// warp per node; lane holds feature pair (2*lane, 2*lane+1); fp32 accumulation.
__global__ void __launch_bounds__(256) k_gather(int layer, int N)
{
    __shared__ float ssum[64], ssq[64];
    int tid  = threadIdx.x;
    int lane = tid & 31;
    int wid  = tid >> 5;
    if (tid < 64) { ssum[tid] = 0.f; ssq[tid] = 0.f; }
    __syncthreads();

    float2 lsum = make_float2(0.f, 0.f);
    float2 lsq  = make_float2(0.f, 0.f);

    const __half2* base = (const __half2*)g_tsch;
    int warps = gridDim.x * 8;
    for (int n = blockIdx.x * 8 + wid; n < N; n += warps) {
        int s0 = g_rowptr[n];
        int s1 = g_rowptr[n + 1];
        float2 acc = __half22float2(base[n * 32 + lane]);   // self loop term
        int e = s0;
        for (; e + 4 <= s1; e += 4) {
            int a = g_csrc[e + 0];
            int b = g_csrc[e + 1];
            int c = g_csrc[e + 2];
            int d = g_csrc[e + 3];
            float2 v0 = __half22float2(base[a * 32 + lane]);
            float2 v1 = __half22float2(base[b * 32 + lane]);
            float2 v2 = __half22float2(base[c * 32 + lane]);
            float2 v3 = __half22float2(base[d * 32 + lane]);
            acc.x += (v0.x + v1.x) + (v2.x + v3.x);
            acc.y += (v0.y + v1.y) + (v2.y + v3.y);
        }
        for (; e < s1; ++e) {
            float2 v = __half22float2(base[g_csrc[e] * 32 + lane]);
            acc.x += v.x; acc.y += v.y;
        }
        float dv = g_dinv[n];
        float2 yv = make_float2(acc.x * dv, acc.y * dv);
        ((float2*)g_y)[n * 32 + lane] = yv;
        lsum.x += yv.x; lsum.y += yv.y;
        lsq.x  += yv.x * yv.x; lsq.y += yv.y * yv.y;
    }

    atomicAdd(&ssum[lane * 2 + 0], lsum.x);
    atomicAdd(&ssum[lane * 2 + 1], lsum.y);
    atomicAdd(&ssq[lane * 2 + 0], lsq.x);
    atomicAdd(&ssq[lane * 2 + 1], lsq.y);
    __syncthreads();
    if (tid < 64) {
        atomicAdd(&g_stats[layer * 128 + tid], ssum[tid]);
        atomicAdd(&g_stats[layer * 128 + 64 + tid], ssq[tid]);
    }
}

// ---------------- pooling: BN+ReLU fused, run-length segment-sum (batch sorted) ----
#define PCHUNK 128
__global__ void __launch_bounds__(256) k_pool(const int* __restrict__ batch,
                                              const float* __restrict__ gammas,
                                              const float* __restrict__ betas,
                                              int layer, int N)
{
    int lane = threadIdx.x & 31;
    int warp = (blockIdx.x * blockDim.x + threadIdx.x) >> 5;
    int n0 = warp * PCHUNK;
    if (n0 >= N) return;
    int n1 = min(n0 + PCHUNK, N);

    float invN = 1.0f / (float)N;
    int c0 = lane * 2, c1 = c0 + 1;
    float m0 = g_stats[layer * 128 + c0] * invN;
    float m1 = g_stats[layer * 128 + c1] * invN;
    float v0 = g_stats[layer * 128 + 64 + c0] * invN - m0 * m0;
    float v1 = g_stats[layer * 128 + 64 + c1] * invN - m1 * m1;
    float s0 = gammas[layer * 64 + c0] * rsqrtf(v0 + BN_EPS);
    float s1 = gammas[layer * 64 + c1] * rsqrtf(v1 + BN_EPS);
    float h0 = betas[layer * 64 + c0] - m0 * s0;
    float h1 = betas[layer * 64 + c1] - m1 * s1;

    const float2* y = (const float2*)g_y;
    int   cur = batch[n0];
    float2 acc = make_float2(0.f, 0.f);
    int   cnt = 0;
    for (int n = n0; n < n1; n++) {
        int g = batch[n];
        if (g != cur) {
            atomicAdd(&g_psum[cur * 64 + c0], acc.x);
            atomicAdd(&g_psum[cur * 64 + c1], acc.y);
            if (lane == 0) atomicAdd(&g_pcnt[cur], cnt);
            acc = make_float2(0.f, 0.f); cnt = 0; cur = g;
        }
        float2 t = y[n * 32 + lane];
        t.x = fmaxf(fmaf(t.x, s0, h0), 0.f);
        t.y = fmaxf(fmaf(t.y, s1, h1), 0.f);
        acc.x += t.x; acc.y += t.y; cnt++;
    }
    atomicAdd(&g_psum[cur * 64 + c0], acc.x);
    atomicAdd(&g_psum[cur * 64 + c1], acc.y);
    if (lane == 0) atomicAdd(&g_pcnt[cur], cnt);
}

__global__ void k_div(int G, float* __restrict__ out)
{
    int t = blockIdx.x * blockDim.x + threadIdx.x;
    if (t < G * 64) {
        float c = (float)g_pcnt[t >> 6];
        out[t] = g_psum[t] / fmaxf(c, 1.0f);
    }
}

// ---------------- launch ----------------
extern "C" void kernel_launch(void* const* d_in, const int* in_sizes, int n_in,
                              void* d_out, int out_size)
{
    const float* x      = (const float*)d_in[0];
    const int*   ei     = (const int*)d_in[1];     // int32 (JAX x64 disabled)
    const int*   batch  = (const int*)d_in[2];     // int32
    const float* Ws     = (const float*)d_in[3];
    // d_in[4] = bs: cancels exactly through BatchNorm (uniform shift), skipped.
    const float* gammas = (const float*)d_in[5];
    const float* betas  = (const float*)d_in[6];

    int N = in_sizes[0] / 64;
    int E = in_sizes[1] / 2;
    int G = out_size / 64;

    void *p_deg, *p_stats, *p_psum, *p_pcnt, *p_y;
    cudaGetSymbolAddress(&p_deg, g_deg);
    cudaGetSymbolAddress(&p_stats, g_stats);
    cudaGetSymbolAddress(&p_psum, g_psum);
    cudaGetSymbolAddress(&p_pcnt, g_pcnt);
    cudaGetSymbolAddress(&p_y, g_y);

    cudaMemsetAsync(p_deg, 0, (size_t)N * sizeof(int));
    cudaMemsetAsync(p_stats, 0, NLAYERS * 128 * sizeof(float));
    cudaMemsetAsync(p_psum, 0, (size_t)G * 64 * sizeof(float));
    cudaMemsetAsync(p_pcnt, 0, (size_t)G * sizeof(int));

    const int tb = 256;
    k_degree<<<(E + tb - 1) / tb, tb>>>(ei, E);

    int nb = (N + 1023) / 1024;
    k_scan1<<<nb, 1024>>>(N);
    k_scan2<<<1, 1024>>>(nb);
    k_scan3<<<(N + tb - 1) / tb, tb>>>(N, E);
    k_fill<<<(E + tb - 1) / tb, tb>>>(ei, E);

    for (int l = 0; l < NLAYERS; ++l) {
        const float* A = (l == 0) ? x : (const float*)p_y;
        k_transform<<<(N + 127) / 128, 128>>>(A, Ws + (size_t)l * 64 * 64,
                                              gammas, betas, l, N, (l > 0) ? 1 : 0);
        k_gather<<<1184, 256>>>(l, N);
    }

    int pwarps  = (N + PCHUNK - 1) / PCHUNK;
    int pblocks = (pwarps + 7) / 8;
    k_pool<<<pblocks, 256>>>(batch, gammas, betas, NLAYERS - 1, N);
    k_div<<<(G * 64 + tb - 1) / tb, tb>>>(G, (float*)d_out);
}

// round 10
// speedup vs baseline: 2.2638x; 1.3275x over previous
#include <cuda_runtime.h>
#include <cuda_fp16.h>
#include <cstdint>

#define D 64
#define MAXN 100000
#define MAXE 1600000
#define NLAYERS 3
#define BN_EPS 1e-5f

// ---------------- scratch (device globals; no allocation allowed) ----------------
__device__ __half g_tsch[MAXN * D];      // fp16 messages: dinv[n] * (act(h)[n] @ W)
__device__ __half g_yh[MAXN * D];        // fp16 pre-BN aggregated layer output
__device__ float  g_dinv[MAXN];
__device__ int    g_deg[MAXN];
__device__ int    g_rowptr[MAXN + 1];
__device__ int    g_cnt[MAXN];
__device__ int    g_csrc[MAXE];
__device__ float  g_stats[NLAYERS * 2 * D];  // per layer: [64 sums][64 sumsqs]
__device__ float  g_psum[128 * D];
__device__ int    g_pcnt[128];
__device__ int    g_bsums[1024];

// ---------------- helpers ----------------
__device__ __forceinline__ uint32_t s2u(const void* p) {
    return (uint32_t)__cvta_generic_to_shared(p);
}
#define SWZ(off) ((off) ^ (((off) >> 3) & 0x70))

__device__ __forceinline__ void ldm_x4(uint32_t& r0, uint32_t& r1, uint32_t& r2, uint32_t& r3,
                                       uint32_t addr) {
    asm volatile("ldmatrix.sync.aligned.m8n8.x4.shared.b16 {%0,%1,%2,%3}, [%4];"
                 : "=r"(r0), "=r"(r1), "=r"(r2), "=r"(r3) : "r"(addr));
}
__device__ __forceinline__ void ldm_x4t(uint32_t& r0, uint32_t& r1, uint32_t& r2, uint32_t& r3,
                                        uint32_t addr) {
    asm volatile("ldmatrix.sync.aligned.m8n8.x4.trans.shared.b16 {%0,%1,%2,%3}, [%4];"
                 : "=r"(r0), "=r"(r1), "=r"(r2), "=r"(r3) : "r"(addr));
}
__device__ __forceinline__ void mma16816(float* c, const uint32_t* a, const uint32_t* b) {
    asm volatile("mma.sync.aligned.m16n8k16.row.col.f32.f16.f16.f32 "
                 "{%0,%1,%2,%3}, {%4,%5,%6,%7}, {%8,%9}, {%0,%1,%2,%3};"
                 : "+f"(c[0]), "+f"(c[1]), "+f"(c[2]), "+f"(c[3])
                 : "r"(a[0]), "r"(a[1]), "r"(a[2]), "r"(a[3]), "r"(b[0]), "r"(b[1]));
}

// ---------------- graph preprocessing ----------------
__global__ void k_degree(const int* __restrict__ ei, int E) {
    int i = blockIdx.x * blockDim.x + threadIdx.x;
    const int4* dst4 = (const int4*)(ei + E);
    int E4 = E >> 2;
    if (i < E4) {
        int4 d = dst4[i];
        atomicAdd(&g_deg[d.x], 1);
        atomicAdd(&g_deg[d.y], 1);
        atomicAdd(&g_deg[d.z], 1);
        atomicAdd(&g_deg[d.w], 1);
    }
    int tail = E4 * 4 + i;
    if (i < (E & 3)) atomicAdd(&g_deg[ei[E + tail]], 1);
}

// block-wise exclusive scan of g_deg -> g_rowptr (partial), block totals -> g_bsums
__global__ void k_scan1(int N) {
    __shared__ int s[1024];
    int t = threadIdx.x;
    int i = blockIdx.x * 1024 + t;
    int v = (i < N) ? g_deg[i] : 0;
    s[t] = v;
    __syncthreads();
    for (int off = 1; off < 1024; off <<= 1) {
        int x = (t >= off) ? s[t - off] : 0;
        __syncthreads();
        s[t] += x;
        __syncthreads();
    }
    if (i < N) g_rowptr[i] = s[t] - v;      // exclusive
    if (t == 1023) g_bsums[blockIdx.x] = s[t];
}

__global__ void k_scan2(int nb) {
    __shared__ int s[1024];
    int t = threadIdx.x;
    int v = (t < nb) ? g_bsums[t] : 0;
    s[t] = v;
    __syncthreads();
    for (int off = 1; off < 1024; off <<= 1) {
        int x = (t >= off) ? s[t - off] : 0;
        __syncthreads();
        s[t] += x;
        __syncthreads();
    }
    if (t < nb) g_bsums[t] = s[t] - v;      // exclusive block offsets
}

__global__ void k_scan3(int N, int E) {
    int i = blockIdx.x * blockDim.x + threadIdx.x;
    if (i < N) {
        int r = g_rowptr[i] + g_bsums[i >> 10];
        g_rowptr[i] = r;
        g_cnt[i] = r;                              // fill cursor
        g_dinv[i] = rsqrtf((float)(g_deg[i] + 1)); // +1 self loop
    }
    if (i == 0) g_rowptr[N] = E;
}

__global__ void k_fill(const int* __restrict__ ei, int E) {
    int i = blockIdx.x * blockDim.x + threadIdx.x;
    const int4* src4 = (const int4*)ei;
    const int4* dst4 = (const int4*)(ei + E);
    int E4 = E >> 2;
    if (i < E4) {
        int4 s = src4[i];
        int4 d = dst4[i];
        g_csrc[atomicAdd(&g_cnt[d.x], 1)] = s.x;
        g_csrc[atomicAdd(&g_cnt[d.y], 1)] = s.y;
        g_csrc[atomicAdd(&g_cnt[d.z], 1)] = s.z;
        g_csrc[atomicAdd(&g_cnt[d.w], 1)] = s.w;
    }
    int tail = E4 * 4 + i;
    if (i < (E & 3)) {
        int s = ei[tail];
        int d = ei[E + tail];
        g_csrc[atomicAdd(&g_cnt[d], 1)] = s;
    }
}

// ---------------- tensor-core transform: msgs = dinv * (act(A) @ W) -> fp16 ---------
// act = identity for layer 0 (fp32 input), BN(prev stats)+ReLU otherwise (fp16 input).
// Block: 256 threads = 8 warps, 256 rows x 64 cols; warp = 32 rows (2 m16 tiles).
__global__ void __launch_bounds__(256) k_mm(
    const void* __restrict__ Aptr, const float* __restrict__ W,
    const float* __restrict__ gammas, const float* __restrict__ betas,
    int layer, int N, int apply_bn, int a_is_half)
{
    __shared__ __align__(16) char sA[256 * 128];   // 256 rows x 64 fp16, SW128
    __shared__ __align__(16) char sW[64 * 128];    // 64 k  x 64 fp16, SW128
    __shared__ float sdinv[256];
    __shared__ float sc[64], sh[64];

    int tid  = threadIdx.x;
    int row0 = blockIdx.x * 256;

    if (tid < 64) {
        if (apply_bn) {
            float invN = 1.0f / (float)N;
            int   pl   = layer - 1;
            float mean = g_stats[pl * 128 + tid] * invN;
            float var  = g_stats[pl * 128 + 64 + tid] * invN - mean * mean;
            float s    = gammas[pl * 64 + tid] * rsqrtf(var + BN_EPS);
            sc[tid] = s;
            sh[tid] = betas[pl * 64 + tid] - mean * s;
        } else {
            sc[tid] = 1.0f;
            sh[tid] = 0.0f;
        }
    }
    {
        int n = row0 + tid;
        sdinv[tid] = (n < N) ? g_dinv[n] : 0.f;
    }

    // W fp32 -> fp16 smem (SW128). thread t: k = t>>2, 16 cols at n0 = (t&3)*16.
    {
        int k  = tid >> 2;
        int n0 = (tid & 3) * 16;
        const float4* w4 = (const float4*)(W + k * 64 + n0);
        float4 a = w4[0], b = w4[1], c = w4[2], d = w4[3];
        __half2 h[8];
        h[0] = __floats2half2_rn(a.x, a.y); h[1] = __floats2half2_rn(a.z, a.w);
        h[2] = __floats2half2_rn(b.x, b.y); h[3] = __floats2half2_rn(b.z, b.w);
        h[4] = __floats2half2_rn(c.x, c.y); h[5] = __floats2half2_rn(c.z, c.w);
        h[6] = __floats2half2_rn(d.x, d.y); h[7] = __floats2half2_rn(d.z, d.w);
        int off = k * 128 + n0 * 2;
        *(uint4*)&sW[SWZ(off)]      = *(uint4*)&h[0];
        *(uint4*)&sW[SWZ(off + 16)] = *(uint4*)&h[4];
    }
    __syncthreads();   // sc/sh ready (needed for BN at A-load)

    // A tile load (+BN+ReLU) -> fp16 smem (SW128). 2048 16B-chunks, 8 per thread.
#pragma unroll
    for (int i = 0; i < 8; i++) {
        int ch  = i * 256 + tid;
        int r   = ch >> 3;          // 0..255
        int c8  = ch & 7;           // 8-col chunk
        int n   = row0 + r;
        float v[8];
        if (n < N) {
            if (a_is_half) {
                uint4 u = ((const uint4*)Aptr)[n * 8 + c8];
                const __half2* hp = (const __half2*)&u;
#pragma unroll
                for (int j = 0; j < 4; j++) {
                    float2 f = __half22float2(hp[j]);
                    v[j * 2 + 0] = f.x;
                    v[j * 2 + 1] = f.y;
                }
            } else {
                float4 p = ((const float4*)Aptr)[n * 16 + c8 * 2];
                float4 q = ((const float4*)Aptr)[n * 16 + c8 * 2 + 1];
                v[0] = p.x; v[1] = p.y; v[2] = p.z; v[3] = p.w;
                v[4] = q.x; v[5] = q.y; v[6] = q.z; v[7] = q.w;
            }
        } else {
#pragma unroll
            for (int j = 0; j < 8; j++) v[j] = 0.f;
        }
        if (apply_bn) {
            int c0 = c8 * 8;
#pragma unroll
            for (int j = 0; j < 8; j++)
                v[j] = fmaxf(fmaf(v[j], sc[c0 + j], sh[c0 + j]), 0.f);
        }
        __half2 h[4];
#pragma unroll
        for (int j = 0; j < 4; j++) h[j] = __floats2half2_rn(v[j * 2], v[j * 2 + 1]);
        *(uint4*)&sA[SWZ(r * 128 + c8 * 16)] = *(uint4*)&h[0];
    }
    __syncthreads();

    // MMA mainloop
    int lane  = tid & 31;
    int warp  = tid >> 5;
    int rbase = warp * 32;

    float acc[2][8][4];
#pragma unroll
    for (int m = 0; m < 2; m++)
#pragma unroll
        for (int nt = 0; nt < 8; nt++)
#pragma unroll
            for (int j = 0; j < 4; j++) acc[m][nt][j] = 0.f;

    uint32_t sA_u = s2u(sA);
    uint32_t sW_u = s2u(sW);
    int lr  = lane & 15;        // row / k within 16
    int lhi = lane >> 4;        // 16B sub-block select

#pragma unroll
    for (int ks = 0; ks < 4; ks++) {
        uint32_t a[2][4];
#pragma unroll
        for (int m = 0; m < 2; m++) {
            int off = (rbase + m * 16 + lr) * 128 + (ks * 16 + lhi * 8) * 2;
            ldm_x4(a[m][0], a[m][1], a[m][2], a[m][3], sA_u + SWZ(off));
        }
        uint32_t b[8][2];
#pragma unroll
        for (int np = 0; np < 4; np++) {
            int off = (ks * 16 + lr) * 128 + (np * 16 + lhi * 8) * 2;
            uint32_t r0, r1, r2, r3;
            ldm_x4t(r0, r1, r2, r3, sW_u + SWZ(off));
            b[np * 2 + 0][0] = r0; b[np * 2 + 0][1] = r1;
            b[np * 2 + 1][0] = r2; b[np * 2 + 1][1] = r3;
        }
#pragma unroll
        for (int m = 0; m < 2; m++)
#pragma unroll
            for (int nt = 0; nt < 8; nt++)
                mma16816(acc[m][nt], a[m], b[nt]);
    }

    // epilogue: scale by dinv, fp16 store
    int q = lane >> 2;          // row group 0..7
    int c = lane & 3;           // col pair 0..3
#pragma unroll
    for (int m = 0; m < 2; m++) {
        int lr0 = rbase + m * 16 + q;
        int r0  = row0 + lr0;
        int r1  = r0 + 8;
        float d0 = sdinv[lr0];
        float d1 = sdinv[lr0 + 8];
#pragma unroll
        for (int nt = 0; nt < 8; nt++) {
            int ci = nt * 4 + c;   // half2 index within row
            if (r0 < N)
                ((__half2*)g_tsch)[r0 * 32 + ci] =
                    __floats2half2_rn(acc[m][nt][0] * d0, acc[m][nt][1] * d0);
            if (r1 < N)
                ((__half2*)g_tsch)[r1 * 32 + ci] =
                    __floats2half2_rn(acc[m][nt][2] * d1, acc[m][nt][3] * d1);
        }
    }
}

// ---------------- CSR gather-aggregate (fp16 msgs) + fused BN stats ----------------
// warp per node; lane holds feature pair (2*lane, 2*lane+1); fp32 accumulation.
__global__ void __launch_bounds__(256) k_gather(int layer, int N)
{
    __shared__ float ssum[64], ssq[64];
    int tid  = threadIdx.x;
    int lane = tid & 31;
    int wid  = tid >> 5;
    if (tid < 64) { ssum[tid] = 0.f; ssq[tid] = 0.f; }
    __syncthreads();

    float2 lsum = make_float2(0.f, 0.f);
    float2 lsq  = make_float2(0.f, 0.f);

    const __half2* base = (const __half2*)g_tsch;
    int warps = gridDim.x * 8;
    for (int n = blockIdx.x * 8 + wid; n < N; n += warps) {
        int s0 = g_rowptr[n];
        int s1 = g_rowptr[n + 1];
        float2 acc = __half22float2(base[n * 32 + lane]);   // self loop term
        int e = s0;
        for (; e + 4 <= s1; e += 4) {
            int a = g_csrc[e + 0];
            int b = g_csrc[e + 1];
            int c = g_csrc[e + 2];
            int d = g_csrc[e + 3];
            float2 v0 = __half22float2(base[a * 32 + lane]);
            float2 v1 = __half22float2(base[b * 32 + lane]);
            float2 v2 = __half22float2(base[c * 32 + lane]);
            float2 v3 = __half22float2(base[d * 32 + lane]);
            acc.x += (v0.x + v1.x) + (v2.x + v3.x);
            acc.y += (v0.y + v1.y) + (v2.y + v3.y);
        }
        for (; e < s1; ++e) {
            float2 v = __half22float2(base[g_csrc[e] * 32 + lane]);
            acc.x += v.x; acc.y += v.y;
        }
        float dv = g_dinv[n];
        float2 yv = make_float2(acc.x * dv, acc.y * dv);
        ((__half2*)g_yh)[n * 32 + lane] = __floats2half2_rn(yv.x, yv.y);
        lsum.x += yv.x; lsum.y += yv.y;
        lsq.x  += yv.x * yv.x; lsq.y += yv.y * yv.y;
    }

    atomicAdd(&ssum[lane * 2 + 0], lsum.x);
    atomicAdd(&ssum[lane * 2 + 1], lsum.y);
    atomicAdd(&ssq[lane * 2 + 0], lsq.x);
    atomicAdd(&ssq[lane * 2 + 1], lsq.y);
    __syncthreads();
    if (tid < 64) {
        atomicAdd(&g_stats[layer * 128 + tid], ssum[tid]);
        atomicAdd(&g_stats[layer * 128 + 64 + tid], ssq[tid]);
    }
}

// ---------------- pooling: BN+ReLU fused, run-length segment-sum (batch sorted) ----
#define PCHUNK 128
__global__ void __launch_bounds__(256) k_pool(const int* __restrict__ batch,
                                              const float* __restrict__ gammas,
                                              const float* __restrict__ betas,
                                              int layer, int N)
{
    int lane = threadIdx.x & 31;
    int warp = (blockIdx.x * blockDim.x + threadIdx.x) >> 5;
    int n0 = warp * PCHUNK;
    if (n0 >= N) return;
    int n1 = min(n0 + PCHUNK, N);

    float invN = 1.0f / (float)N;
    int c0 = lane * 2, c1 = c0 + 1;
    float m0 = g_stats[layer * 128 + c0] * invN;
    float m1 = g_stats[layer * 128 + c1] * invN;
    float v0 = g_stats[layer * 128 + 64 + c0] * invN - m0 * m0;
    float v1 = g_stats[layer * 128 + 64 + c1] * invN - m1 * m1;
    float s0 = gammas[layer * 64 + c0] * rsqrtf(v0 + BN_EPS);
    float s1 = gammas[layer * 64 + c1] * rsqrtf(v1 + BN_EPS);
    float h0 = betas[layer * 64 + c0] - m0 * s0;
    float h1 = betas[layer * 64 + c1] - m1 * s1;

    const __half2* y = (const __half2*)g_yh;
    int    cur = batch[n0];
    float2 acc = make_float2(0.f, 0.f);
    int    cnt = 0;
    for (int n = n0; n < n1; n++) {
        int g = batch[n];
        if (g != cur) {
            atomicAdd(&g_psum[cur * 64 + c0], acc.x);
            atomicAdd(&g_psum[cur * 64 + c1], acc.y);
            if (lane == 0) atomicAdd(&g_pcnt[cur], cnt);
            acc = make_float2(0.f, 0.f); cnt = 0; cur = g;
        }
        float2 t = __half22float2(y[n * 32 + lane]);
        t.x = fmaxf(fmaf(t.x, s0, h0), 0.f);
        t.y = fmaxf(fmaf(t.y, s1, h1), 0.f);
        acc.x += t.x; acc.y += t.y; cnt++;
    }
    atomicAdd(&g_psum[cur * 64 + c0], acc.x);
    atomicAdd(&g_psum[cur * 64 + c1], acc.y);
    if (lane == 0) atomicAdd(&g_pcnt[cur], cnt);
}

__global__ void k_div(int G, float* __restrict__ out)
{
    int t = blockIdx.x * blockDim.x + threadIdx.x;
    if (t < G * 64) {
        float c = (float)g_pcnt[t >> 6];
        out[t] = g_psum[t] / fmaxf(c, 1.0f);
    }
}

// ---------------- launch ----------------
extern "C" void kernel_launch(void* const* d_in, const int* in_sizes, int n_in,
                              void* d_out, int out_size)
{
    const float* x      = (const float*)d_in[0];
    const int*   ei     = (const int*)d_in[1];     // int32 (JAX x64 disabled)
    const int*   batch  = (const int*)d_in[2];     // int32
    const float* Ws     = (const float*)d_in[3];
    // d_in[4] = bs: cancels exactly through BatchNorm (uniform shift), skipped.
    const float* gammas = (const float*)d_in[5];
    const float* betas  = (const float*)d_in[6];

    int N = in_sizes[0] / 64;
    int E = in_sizes[1] / 2;
    int G = out_size / 64;

    void *p_deg, *p_stats, *p_psum, *p_pcnt, *p_yh;
    cudaGetSymbolAddress(&p_deg, g_deg);
    cudaGetSymbolAddress(&p_stats, g_stats);
    cudaGetSymbolAddress(&p_psum, g_psum);
    cudaGetSymbolAddress(&p_pcnt, g_pcnt);
    cudaGetSymbolAddress(&p_yh, g_yh);

    cudaMemsetAsync(p_deg, 0, (size_t)N * sizeof(int));
    cudaMemsetAsync(p_stats, 0, NLAYERS * 128 * sizeof(float));
    cudaMemsetAsync(p_psum, 0, (size_t)G * 64 * sizeof(float));
    cudaMemsetAsync(p_pcnt, 0, (size_t)G * sizeof(int));

    const int tb = 256;
    int E4 = E >> 2;
    k_degree<<<(max(E4, 1) + tb - 1) / tb, tb>>>(ei, E);

    int nb = (N + 1023) / 1024;
    k_scan1<<<nb, 1024>>>(N);
    k_scan2<<<1, 1024>>>(nb);
    k_scan3<<<(N + tb - 1) / tb, tb>>>(N, E);
    k_fill<<<(max(E4, 1) + tb - 1) / tb, tb>>>(ei, E);

    for (int l = 0; l < NLAYERS; ++l) {
        const void* A = (l == 0) ? (const void*)x : (const void*)p_yh;
        k_mm<<<(N + 255) / 256, 256>>>(A, Ws + (size_t)l * 64 * 64,
                                       gammas, betas, l, N,
                                       (l > 0) ? 1 : 0, (l > 0) ? 1 : 0);
        k_gather<<<1184, 256>>>(l, N);
    }

    int pwarps  = (N + PCHUNK - 1) / PCHUNK;
    int pblocks = (pwarps + 7) / 8;
    k_pool<<<pblocks, 256>>>(batch, gammas, betas, NLAYERS - 1, N);
    k_div<<<(G * 64 + tb - 1) / tb, tb>>>(G, (float*)d_out);
}

// round 13
// speedup vs baseline: 2.7622x; 1.2201x over previous
#include <cuda_runtime.h>
#include <cuda_fp16.h>
#include <cstdint>

#define D 64
#define MAXN 100000
#define MAXE 1600000
#define NLAYERS 3
#define BN_EPS 1e-5f

// ---------------- scratch (device globals; no allocation allowed) ----------------
__device__ __half g_tsch[MAXN * D];      // fp16 messages: dinv[n] * (act(h)[n] @ W)
__device__ __half g_yh[MAXN * D];        // fp16 pre-BN aggregated layer output
__device__ float  g_dinv[MAXN];
__device__ int    g_deg[MAXN];
__device__ int    g_rowptr[MAXN + 1];
__device__ int    g_cnt[MAXN];
__device__ int    g_csrc[MAXE];
__device__ float  g_stats[NLAYERS * 2 * D];  // per layer: [64 sums][64 sumsqs]
__device__ float  g_psum[128 * D];
__device__ int    g_pcnt[128];
__device__ int    g_scanpub[128];            // 0x40000000 | block_aggregate

// ---------------- helpers ----------------
__device__ __forceinline__ uint32_t s2u(const void* p) {
    return (uint32_t)__cvta_generic_to_shared(p);
}
#define SWZ(off) ((off) ^ (((off) >> 3) & 0x70))

__device__ __forceinline__ void ldm_x4(uint32_t& r0, uint32_t& r1, uint32_t& r2, uint32_t& r3,
                                       uint32_t addr) {
    asm volatile("ldmatrix.sync.aligned.m8n8.x4.shared.b16 {%0,%1,%2,%3}, [%4];"
                 : "=r"(r0), "=r"(r1), "=r"(r2), "=r"(r3) : "r"(addr));
}
__device__ __forceinline__ void ldm_x4t(uint32_t& r0, uint32_t& r1, uint32_t& r2, uint32_t& r3,
                                        uint32_t addr) {
    asm volatile("ldmatrix.sync.aligned.m8n8.x4.trans.shared.b16 {%0,%1,%2,%3}, [%4];"
                 : "=r"(r0), "=r"(r1), "=r"(r2), "=r"(r3) : "r"(addr));
}
__device__ __forceinline__ void mma16816(float* c, const uint32_t* a, const uint32_t* b) {
    asm volatile("mma.sync.aligned.m16n8k16.row.col.f32.f16.f16.f32 "
                 "{%0,%1,%2,%3}, {%4,%5,%6,%7}, {%8,%9}, {%0,%1,%2,%3};"
                 : "+f"(c[0]), "+f"(c[1]), "+f"(c[2]), "+f"(c[3])
                 : "r"(a[0]), "r"(a[1]), "r"(a[2]), "r"(a[3]), "r"(b[0]), "r"(b[1]));
}

// ---------------- fused zero (replaces 4 memsets) ----------------
__global__ void k_zero(int N) {
    int i = blockIdx.x * blockDim.x + threadIdx.x;
    int stride = gridDim.x * blockDim.x;
    for (int j = i; j < N; j += stride) g_deg[j] = 0;
    if (i < NLAYERS * 2 * D) g_stats[i] = 0.f;
    if (i < 128 * D) g_psum[i] = 0.f;
    if (i < 128) { g_pcnt[i] = 0; g_scanpub[i] = 0; }
}

// ---------------- graph preprocessing ----------------
__global__ void k_degree(const int* __restrict__ ei, int E) {
    int i = blockIdx.x * blockDim.x + threadIdx.x;
    const int4* dst4 = (const int4*)(ei + E);
    int E4 = E >> 2;
    if (i < E4) {
        int4 d = dst4[i];
        atomicAdd(&g_deg[d.x], 1);
        atomicAdd(&g_deg[d.y], 1);
        atomicAdd(&g_deg[d.z], 1);
        atomicAdd(&g_deg[d.w], 1);
    }
    int tail = E4 * 4 + i;
    if (i < (E & 3)) atomicAdd(&g_deg[ei[E + tail]], 1);
}

// single-kernel exclusive scan (publish/poll block aggregates; grid <= 128 blocks,
// all co-resident in wave 1, publishers never poll -> deadlock-free)
// also emits fill cursor + dinv + rowptr[N].
__global__ void __launch_bounds__(1024) k_scanall(int N, int E) {
    __shared__ int s[1024];
    __shared__ int s_off;
    int t = threadIdx.x;
    int b = blockIdx.x;
    int i = b * 1024 + t;
    int d = (i < N) ? g_deg[i] : 0;
    s[t] = d;
    __syncthreads();
    for (int off = 1; off < 1024; off <<= 1) {
        int x = (t >= off) ? s[t - off] : 0;
        __syncthreads();
        s[t] += x;
        __syncthreads();
    }
    if (t == 1023) atomicExch(&g_scanpub[b], 0x40000000 | s[1023]);
    if (t < 32) {
        int sum = 0;
        for (int j = t; j < b; j += 32) {
            int v;
            do { v = atomicAdd(&g_scanpub[j], 0); } while (v == 0);
            sum += v & 0x3FFFFFFF;
        }
#pragma unroll
        for (int o = 16; o; o >>= 1) sum += __shfl_xor_sync(0xffffffffu, sum, o);
        if (t == 0) s_off = sum;
    }
    __syncthreads();
    if (i < N) {
        int r = s_off + s[t] - d;          // exclusive prefix
        g_rowptr[i] = r;
        g_cnt[i] = r;                      // fill cursor
        g_dinv[i] = rsqrtf((float)(d + 1)); // +1 self loop
    }
    if (i == 0) g_rowptr[N] = E;
}

__global__ void k_fill(const int* __restrict__ ei, int E) {
    int i = blockIdx.x * blockDim.x + threadIdx.x;
    const int4* src4 = (const int4*)ei;
    const int4* dst4 = (const int4*)(ei + E);
    int E4 = E >> 2;
    if (i < E4) {
        int4 s = src4[i];
        int4 d = dst4[i];
        g_csrc[atomicAdd(&g_cnt[d.x], 1)] = s.x;
        g_csrc[atomicAdd(&g_cnt[d.y], 1)] = s.y;
        g_csrc[atomicAdd(&g_cnt[d.z], 1)] = s.z;
        g_csrc[atomicAdd(&g_cnt[d.w], 1)] = s.w;
    }
    int tail = E4 * 4 + i;
    if (i < (E & 3)) {
        int s = ei[tail];
        int d = ei[E + tail];
        g_csrc[atomicAdd(&g_cnt[d], 1)] = s;
    }
}

// ---------------- tensor-core transform: msgs = dinv * (act(A) @ W) -> fp16 ---------
// act = identity for layer 0 (fp32 input), BN(prev stats)+ReLU otherwise (fp16 input).
// Block: 256 threads = 8 warps, 256 rows x 64 cols; warp = 32 rows (2 m16 tiles).
__global__ void __launch_bounds__(256) k_mm(
    const void* __restrict__ Aptr, const float* __restrict__ W,
    const float* __restrict__ gammas, const float* __restrict__ betas,
    int layer, int N, int apply_bn, int a_is_half)
{
    __shared__ __align__(16) char sA[256 * 128];   // 256 rows x 64 fp16, SW128
    __shared__ __align__(16) char sW[64 * 128];    // 64 k  x 64 fp16, SW128
    __shared__ float sdinv[256];
    __shared__ float sc[64], sh[64];

    int tid  = threadIdx.x;
    int row0 = blockIdx.x * 256;

    if (tid < 64) {
        if (apply_bn) {
            float invN = 1.0f / (float)N;
            int   pl   = layer - 1;
            float mean = g_stats[pl * 128 + tid] * invN;
            float var  = g_stats[pl * 128 + 64 + tid] * invN - mean * mean;
            float s    = gammas[pl * 64 + tid] * rsqrtf(var + BN_EPS);
            sc[tid] = s;
            sh[tid] = betas[pl * 64 + tid] - mean * s;
        } else {
            sc[tid] = 1.0f;
            sh[tid] = 0.0f;
        }
    }
    {
        int n = row0 + tid;
        sdinv[tid] = (n < N) ? g_dinv[n] : 0.f;
    }

    // W fp32 -> fp16 smem (SW128). thread t: k = t>>2, 16 cols at n0 = (t&3)*16.
    {
        int k  = tid >> 2;
        int n0 = (tid & 3) * 16;
        const float4* w4 = (const float4*)(W + k * 64 + n0);
        float4 a = w4[0], b = w4[1], c = w4[2], d = w4[3];
        __half2 h[8];
        h[0] = __floats2half2_rn(a.x, a.y); h[1] = __floats2half2_rn(a.z, a.w);
        h[2] = __floats2half2_rn(b.x, b.y); h[3] = __floats2half2_rn(b.z, b.w);
        h[4] = __floats2half2_rn(c.x, c.y); h[5] = __floats2half2_rn(c.z, c.w);
        h[6] = __floats2half2_rn(d.x, d.y); h[7] = __floats2half2_rn(d.z, d.w);
        int off = k * 128 + n0 * 2;
        *(uint4*)&sW[SWZ(off)]      = *(uint4*)&h[0];
        *(uint4*)&sW[SWZ(off + 16)] = *(uint4*)&h[4];
    }
    __syncthreads();   // sc/sh ready (needed for BN at A-load)

    // A tile load (+BN+ReLU) -> fp16 smem (SW128). 2048 16B-chunks, 8 per thread.
#pragma unroll
    for (int i = 0; i < 8; i++) {
        int ch  = i * 256 + tid;
        int r   = ch >> 3;          // 0..255
        int c8  = ch & 7;           // 8-col chunk
        int n   = row0 + r;
        float v[8];
        if (n < N) {
            if (a_is_half) {
                uint4 u = ((const uint4*)Aptr)[n * 8 + c8];
                const __half2* hp = (const __half2*)&u;
#pragma unroll
                for (int j = 0; j < 4; j++) {
                    float2 f = __half22float2(hp[j]);
                    v[j * 2 + 0] = f.x;
                    v[j * 2 + 1] = f.y;
                }
            } else {
                float4 p = ((const float4*)Aptr)[n * 16 + c8 * 2];
                float4 q = ((const float4*)Aptr)[n * 16 + c8 * 2 + 1];
                v[0] = p.x; v[1] = p.y; v[2] = p.z; v[3] = p.w;
                v[4] = q.x; v[5] = q.y; v[6] = q.z; v[7] = q.w;
            }
        } else {
#pragma unroll
            for (int j = 0; j < 8; j++) v[j] = 0.f;
        }
        if (apply_bn) {
            int c0 = c8 * 8;
#pragma unroll
            for (int j = 0; j < 8; j++)
                v[j] = fmaxf(fmaf(v[j], sc[c0 + j], sh[c0 + j]), 0.f);
        }
        __half2 h[4];
#pragma unroll
        for (int j = 0; j < 4; j++) h[j] = __floats2half2_rn(v[j * 2], v[j * 2 + 1]);
        *(uint4*)&sA[SWZ(r * 128 + c8 * 16)] = *(uint4*)&h[0];
    }
    __syncthreads();

    // MMA mainloop
    int lane  = tid & 31;
    int warp  = tid >> 5;
    int rbase = warp * 32;

    float acc[2][8][4];
#pragma unroll
    for (int m = 0; m < 2; m++)
#pragma unroll
        for (int nt = 0; nt < 8; nt++)
#pragma unroll
            for (int j = 0; j < 4; j++) acc[m][nt][j] = 0.f;

    uint32_t sA_u = s2u(sA);
    uint32_t sW_u = s2u(sW);
    int lr  = lane & 15;        // row / k within 16
    int lhi = lane >> 4;        // 16B sub-block select

#pragma unroll
    for (int ks = 0; ks < 4; ks++) {
        uint32_t a[2][4];
#pragma unroll
        for (int m = 0; m < 2; m++) {
            int off = (rbase + m * 16 + lr) * 128 + (ks * 16 + lhi * 8) * 2;
            ldm_x4(a[m][0], a[m][1], a[m][2], a[m][3], sA_u + SWZ(off));
        }
        uint32_t b[8][2];
#pragma unroll
        for (int np = 0; np < 4; np++) {
            int off = (ks * 16 + lr) * 128 + (np * 16 + lhi * 8) * 2;
            uint32_t r0, r1, r2, r3;
            ldm_x4t(r0, r1, r2, r3, sW_u + SWZ(off));
            b[np * 2 + 0][0] = r0; b[np * 2 + 0][1] = r1;
            b[np * 2 + 1][0] = r2; b[np * 2 + 1][1] = r3;
        }
#pragma unroll
        for (int m = 0; m < 2; m++)
#pragma unroll
            for (int nt = 0; nt < 8; nt++)
                mma16816(acc[m][nt], a[m], b[nt]);
    }

    // epilogue: scale by dinv, fp16 store
    int q = lane >> 2;          // row group 0..7
    int c = lane & 3;           // col pair 0..3
#pragma unroll
    for (int m = 0; m < 2; m++) {
        int lr0 = rbase + m * 16 + q;
        int r0  = row0 + lr0;
        int r1  = r0 + 8;
        float d0 = sdinv[lr0];
        float d1 = sdinv[lr0 + 8];
#pragma unroll
        for (int nt = 0; nt < 8; nt++) {
            int ci = nt * 4 + c;   // half2 index within row
            if (r0 < N)
                ((__half2*)g_tsch)[r0 * 32 + ci] =
                    __floats2half2_rn(acc[m][nt][0] * d0, acc[m][nt][1] * d0);
            if (r1 < N)
                ((__half2*)g_tsch)[r1 * 32 + ci] =
                    __floats2half2_rn(acc[m][nt][2] * d1, acc[m][nt][3] * d1);
        }
    }
}

// ---------------- CSR gather-aggregate (fp16 msgs) + fused BN stats ----------------
// warp per node; lane holds feature pair (2*lane, 2*lane+1); fp32 accumulation.
__global__ void __launch_bounds__(256) k_gather(int layer, int N)
{
    __shared__ float ssum[64], ssq[64];
    int tid  = threadIdx.x;
    int lane = tid & 31;
    int wid  = tid >> 5;
    if (tid < 64) { ssum[tid] = 0.f; ssq[tid] = 0.f; }
    __syncthreads();

    float2 lsum = make_float2(0.f, 0.f);
    float2 lsq  = make_float2(0.f, 0.f);

    const __half2* base = (const __half2*)g_tsch;
    int warps = gridDim.x * 8;
    for (int n = blockIdx.x * 8 + wid; n < N; n += warps) {
        int s0 = g_rowptr[n];
        int s1 = g_rowptr[n + 1];
        float2 acc = __half22float2(base[n * 32 + lane]);   // self loop term
        int e = s0;
        for (; e + 8 <= s1; e += 8) {
            int i0 = g_csrc[e + 0];
            int i1 = g_csrc[e + 1];
            int i2 = g_csrc[e + 2];
            int i3 = g_csrc[e + 3];
            int i4 = g_csrc[e + 4];
            int i5 = g_csrc[e + 5];
            int i6 = g_csrc[e + 6];
            int i7 = g_csrc[e + 7];
            float2 v0 = __half22float2(base[i0 * 32 + lane]);
            float2 v1 = __half22float2(base[i1 * 32 + lane]);
            float2 v2 = __half22float2(base[i2 * 32 + lane]);
            float2 v3 = __half22float2(base[i3 * 32 + lane]);
            float2 v4 = __half22float2(base[i4 * 32 + lane]);
            float2 v5 = __half22float2(base[i5 * 32 + lane]);
            float2 v6 = __half22float2(base[i6 * 32 + lane]);
            float2 v7 = __half22float2(base[i7 * 32 + lane]);
            acc.x += ((v0.x + v1.x) + (v2.x + v3.x)) + ((v4.x + v5.x) + (v6.x + v7.x));
            acc.y += ((v0.y + v1.y) + (v2.y + v3.y)) + ((v4.y + v5.y) + (v6.y + v7.y));
        }
        for (; e + 4 <= s1; e += 4) {
            int i0 = g_csrc[e + 0];
            int i1 = g_csrc[e + 1];
            int i2 = g_csrc[e + 2];
            int i3 = g_csrc[e + 3];
            float2 v0 = __half22float2(base[i0 * 32 + lane]);
            float2 v1 = __half22float2(base[i1 * 32 + lane]);
            float2 v2 = __half22float2(base[i2 * 32 + lane]);
            float2 v3 = __half22float2(base[i3 * 32 + lane]);
            acc.x += (v0.x + v1.x) + (v2.x + v3.x);
            acc.y += (v0.y + v1.y) + (v2.y + v3.y);
        }
        for (; e < s1; ++e) {
            float2 v = __half22float2(base[g_csrc[e] * 32 + lane]);
            acc.x += v.x; acc.y += v.y;
        }
        float dv = g_dinv[n];
        float2 yv = make_float2(acc.x * dv, acc.y * dv);
        ((__half2*)g_yh)[n * 32 + lane] = __floats2half2_rn(yv.x, yv.y);
        lsum.x += yv.x; lsum.y += yv.y;
        lsq.x  += yv.x * yv.x; lsq.y += yv.y * yv.y;
    }

    atomicAdd(&ssum[lane * 2 + 0], lsum.x);
    atomicAdd(&ssum[lane * 2 + 1], lsum.y);
    atomicAdd(&ssq[lane * 2 + 0], lsq.x);
    atomicAdd(&ssq[lane * 2 + 1], lsq.y);
    __syncthreads();
    if (tid < 64) {
        atomicAdd(&g_stats[layer * 128 + tid], ssum[tid]);
        atomicAdd(&g_stats[layer * 128 + 64 + tid], ssq[tid]);
    }
}

// ---------------- pooling: BN+ReLU fused, run-length segment-sum (batch sorted) ----
#define PCHUNK 32
__global__ void __launch_bounds__(256) k_pool(const int* __restrict__ batch,
                                              const float* __restrict__ gammas,
                                              const float* __restrict__ betas,
                                              int layer, int N)
{
    int lane = threadIdx.x & 31;
    int warp = (blockIdx.x * blockDim.x + threadIdx.x) >> 5;
    int n0 = warp * PCHUNK;
    if (n0 >= N) return;
    int n1 = min(n0 + PCHUNK, N);

    float invN = 1.0f / (float)N;
    int c0 = lane * 2, c1 = c0 + 1;
    float m0 = g_stats[layer * 128 + c0] * invN;
    float m1 = g_stats[layer * 128 + c1] * invN;
    float v0 = g_stats[layer * 128 + 64 + c0] * invN - m0 * m0;
    float v1 = g_stats[layer * 128 + 64 + c1] * invN - m1 * m1;
    float s0 = gammas[layer * 64 + c0] * rsqrtf(v0 + BN_EPS);
    float s1 = gammas[layer * 64 + c1] * rsqrtf(v1 + BN_EPS);
    float h0 = betas[layer * 64 + c0] - m0 * s0;
    float h1 = betas[layer * 64 + c1] - m1 * s1;

    const __half2* y = (const __half2*)g_yh;
    int    cur = batch[n0];
    float2 acc = make_float2(0.f, 0.f);
    int    cnt = 0;
    for (int n = n0; n < n1; n++) {
        int g = batch[n];
        if (g != cur) {
            atomicAdd(&g_psum[cur * 64 + c0], acc.x);
            atomicAdd(&g_psum[cur * 64 + c1], acc.y);
            if (lane == 0) atomicAdd(&g_pcnt[cur], cnt);
            acc = make_float2(0.f, 0.f); cnt = 0; cur = g;
        }
        float2 t = __half22float2(y[n * 32 + lane]);
        t.x = fmaxf(fmaf(t.x, s0, h0), 0.f);
        t.y = fmaxf(fmaf(t.y, s1, h1), 0.f);
        acc.x += t.x; acc.y += t.y; cnt++;
    }
    atomicAdd(&g_psum[cur * 64 + c0], acc.x);
    atomicAdd(&g_psum[cur * 64 + c1], acc.y);
    if (lane == 0) atomicAdd(&g_pcnt[cur], cnt);
}

__global__ void k_div(int G, float* __restrict__ out)
{
    int t = blockIdx.x * blockDim.x + threadIdx.x;
    if (t < G * 64) {
        float c = (float)g_pcnt[t >> 6];
        out[t] = g_psum[t] / fmaxf(c, 1.0f);
    }
}

// ---------------- launch ----------------
extern "C" void kernel_launch(void* const* d_in, const int* in_sizes, int n_in,
                              void* d_out, int out_size)
{
    const float* x      = (const float*)d_in[0];
    const int*   ei     = (const int*)d_in[1];     // int32 (JAX x64 disabled)
    const int*   batch  = (const int*)d_in[2];     // int32
    const float* Ws     = (const float*)d_in[3];
    // d_in[4] = bs: cancels exactly through BatchNorm (uniform shift), skipped.
    const float* gammas = (const float*)d_in[5];
    const float* betas  = (const float*)d_in[6];

    int N = in_sizes[0] / 64;
    int E = in_sizes[1] / 2;
    int G = out_size / 64;

    void* p_yh;
    cudaGetSymbolAddress(&p_yh, g_yh);

    const int tb = 256;
    int E4 = E >> 2;

    k_zero<<<(N + tb - 1) / tb, tb>>>(N);
    k_degree<<<(max(E4, 1) + tb - 1) / tb, tb>>>(ei, E);

    int nb = (N + 1023) / 1024;   // <= 98 blocks: wave-1 co-resident
    k_scanall<<<nb, 1024>>>(N, E);
    k_fill<<<(max(E4, 1) + tb - 1) / tb, tb>>>(ei, E);

    for (int l = 0; l < NLAYERS; ++l) {
        const void* A = (l == 0) ? (const void*)x : (const void*)p_yh;
        k_mm<<<(N + 255) / 256, 256>>>(A, Ws + (size_t)l * 64 * 64,
                                       gammas, betas, l, N,
                                       (l > 0) ? 1 : 0, (l > 0) ? 1 : 0);
        k_gather<<<1184, 256>>>(l, N);
    }

    int pwarps  = (N + PCHUNK - 1) / PCHUNK;
    int pblocks = (pwarps + 7) / 8;
    k_pool<<<pblocks, 256>>>(batch, gammas, betas, NLAYERS - 1, N);
    k_div<<<(G * 64 + tb - 1) / tb, tb>>>(G, (float*)d_out);
}

// round 14
// speedup vs baseline: 2.7636x; 1.0005x over previous
#include <cuda_runtime.h>
#include <cuda_fp16.h>
#include <cstdint>

#define D 64
#define MAXN 100000
#define MAXE 1600000
#define NLAYERS 3
#define BN_EPS 1e-5f

// ---------------- scratch (device globals; no allocation allowed) ----------------
__device__ __half g_tsch[MAXN * D];      // fp16 messages: dinv[n] * (act(h)[n] @ W)
__device__ __half g_yh[MAXN * D];        // fp16 pre-BN aggregated layer output
__device__ float  g_dinv[MAXN];
__device__ int    g_deg[MAXN];
__device__ int    g_rowptr[MAXN + 1];
__device__ int    g_rank[MAXE];          // per-edge rank within its dst (from degree pass)
__device__ int    g_csrc[MAXE];
__device__ float  g_stats[NLAYERS * 2 * D];  // per layer: [64 sums][64 sumsqs]
__device__ float  g_psum[128 * D];
__device__ int    g_pcnt[128];
__device__ int    g_scanpub[128];            // 0x40000000 | block_aggregate

// ---------------- helpers ----------------
__device__ __forceinline__ uint32_t s2u(const void* p) {
    return (uint32_t)__cvta_generic_to_shared(p);
}
#define SWZ(off) ((off) ^ (((off) >> 3) & 0x70))

__device__ __forceinline__ void ldm_x4(uint32_t& r0, uint32_t& r1, uint32_t& r2, uint32_t& r3,
                                       uint32_t addr) {
    asm volatile("ldmatrix.sync.aligned.m8n8.x4.shared.b16 {%0,%1,%2,%3}, [%4];"
                 : "=r"(r0), "=r"(r1), "=r"(r2), "=r"(r3) : "r"(addr));
}
__device__ __forceinline__ void ldm_x4t(uint32_t& r0, uint32_t& r1, uint32_t& r2, uint32_t& r3,
                                        uint32_t addr) {
    asm volatile("ldmatrix.sync.aligned.m8n8.x4.trans.shared.b16 {%0,%1,%2,%3}, [%4];"
                 : "=r"(r0), "=r"(r1), "=r"(r2), "=r"(r3) : "r"(addr));
}
__device__ __forceinline__ void mma16816(float* c, const uint32_t* a, const uint32_t* b) {
    asm volatile("mma.sync.aligned.m16n8k16.row.col.f32.f16.f16.f32 "
                 "{%0,%1,%2,%3}, {%4,%5,%6,%7}, {%8,%9}, {%0,%1,%2,%3};"
                 : "+f"(c[0]), "+f"(c[1]), "+f"(c[2]), "+f"(c[3])
                 : "r"(a[0]), "r"(a[1]), "r"(a[2]), "r"(a[3]), "r"(b[0]), "r"(b[1]));
}

// ---------------- fused zero (replaces memsets) ----------------
__global__ void k_zero(int N) {
    int i = blockIdx.x * blockDim.x + threadIdx.x;
    int stride = gridDim.x * blockDim.x;
    for (int j = i; j < N; j += stride) g_deg[j] = 0;
    if (i < NLAYERS * 2 * D) g_stats[i] = 0.f;
    if (i < 128 * D) g_psum[i] = 0.f;
    if (i < 128) { g_pcnt[i] = 0; g_scanpub[i] = 0; }
}

// ---------------- graph preprocessing ----------------
// degree histogram; the atomic's return value is the edge's rank within its dst
// (saved coalesced -> makes k_fill atomic-free).
__global__ void k_degree(const int* __restrict__ ei, int E) {
    int i = blockIdx.x * blockDim.x + threadIdx.x;
    const int4* dst4 = (const int4*)(ei + E);
    int E4 = E >> 2;
    if (i < E4) {
        int4 d = dst4[i];
        int4 r;
        r.x = atomicAdd(&g_deg[d.x], 1);
        r.y = atomicAdd(&g_deg[d.y], 1);
        r.z = atomicAdd(&g_deg[d.z], 1);
        r.w = atomicAdd(&g_deg[d.w], 1);
        ((int4*)g_rank)[i] = r;
    }
    int tail = E4 * 4 + i;
    if (i < (E & 3)) g_rank[tail] = atomicAdd(&g_deg[ei[E + tail]], 1);
}

// single-kernel exclusive scan (publish/poll block aggregates; grid <= 128 blocks,
// all co-resident in wave 1, publishers never poll -> deadlock-free)
// also emits dinv + rowptr[N].
__global__ void __launch_bounds__(1024) k_scanall(int N, int E) {
    __shared__ int s[1024];
    __shared__ int s_off;
    int t = threadIdx.x;
    int b = blockIdx.x;
    int i = b * 1024 + t;
    int d = (i < N) ? g_deg[i] : 0;
    s[t] = d;
    __syncthreads();
    for (int off = 1; off < 1024; off <<= 1) {
        int x = (t >= off) ? s[t - off] : 0;
        __syncthreads();
        s[t] += x;
        __syncthreads();
    }
    if (t == 1023) atomicExch(&g_scanpub[b], 0x40000000 | s[1023]);
    if (t < 32) {
        int sum = 0;
        for (int j = t; j < b; j += 32) {
            int v;
            do { v = atomicAdd(&g_scanpub[j], 0); } while (v == 0);
            sum += v & 0x3FFFFFFF;
        }
#pragma unroll
        for (int o = 16; o; o >>= 1) sum += __shfl_xor_sync(0xffffffffu, sum, o);
        if (t == 0) s_off = sum;
    }
    __syncthreads();
    if (i < N) {
        int r = s_off + s[t] - d;           // exclusive prefix
        g_rowptr[i] = r;
        g_dinv[i] = rsqrtf((float)(d + 1)); // +1 self loop
    }
    if (i == 0) g_rowptr[N] = E;
}

// atomic-free CSR fill: pos = rowptr[dst] + rank[edge]
__global__ void k_fill(const int* __restrict__ ei, int E) {
    int i = blockIdx.x * blockDim.x + threadIdx.x;
    const int4* src4  = (const int4*)ei;
    const int4* dst4  = (const int4*)(ei + E);
    const int4* rank4 = (const int4*)g_rank;
    int E4 = E >> 2;
    if (i < E4) {
        int4 s = src4[i];
        int4 d = dst4[i];
        int4 r = rank4[i];
        g_csrc[__ldg(&g_rowptr[d.x]) + r.x] = s.x;
        g_csrc[__ldg(&g_rowptr[d.y]) + r.y] = s.y;
        g_csrc[__ldg(&g_rowptr[d.z]) + r.z] = s.z;
        g_csrc[__ldg(&g_rowptr[d.w]) + r.w] = s.w;
    }
    int tail = E4 * 4 + i;
    if (i < (E & 3)) {
        int s = ei[tail];
        int d = ei[E + tail];
        g_csrc[__ldg(&g_rowptr[d]) + g_rank[tail]] = s;
    }
}

// ---------------- tensor-core transform: msgs = dinv * (act(A) @ W) -> fp16 ---------
// act = identity for layer 0 (fp32 input), BN(prev stats)+ReLU otherwise (fp16 input).
// Block: 256 threads = 8 warps, 256 rows x 64 cols; warp = 32 rows (2 m16 tiles).
__global__ void __launch_bounds__(256) k_mm(
    const void* __restrict__ Aptr, const float* __restrict__ W,
    const float* __restrict__ gammas, const float* __restrict__ betas,
    int layer, int N, int apply_bn, int a_is_half)
{
    __shared__ __align__(16) char sA[256 * 128];   // 256 rows x 64 fp16, SW128
    __shared__ __align__(16) char sW[64 * 128];    // 64 k  x 64 fp16, SW128
    __shared__ float sdinv[256];
    __shared__ float sc[64], sh[64];

    int tid  = threadIdx.x;
    int row0 = blockIdx.x * 256;

    if (tid < 64) {
        if (apply_bn) {
            float invN = 1.0f / (float)N;
            int   pl   = layer - 1;
            float mean = g_stats[pl * 128 + tid] * invN;
            float var  = g_stats[pl * 128 + 64 + tid] * invN - mean * mean;
            float s    = gammas[pl * 64 + tid] * rsqrtf(var + BN_EPS);
            sc[tid] = s;
            sh[tid] = betas[pl * 64 + tid] - mean * s;
        } else {
            sc[tid] = 1.0f;
            sh[tid] = 0.0f;
        }
    }
    {
        int n = row0 + tid;
        sdinv[tid] = (n < N) ? g_dinv[n] : 0.f;
    }

    // W fp32 -> fp16 smem (SW128). thread t: k = t>>2, 16 cols at n0 = (t&3)*16.
    {
        int k  = tid >> 2;
        int n0 = (tid & 3) * 16;
        const float4* w4 = (const float4*)(W + k * 64 + n0);
        float4 a = w4[0], b = w4[1], c = w4[2], d = w4[3];
        __half2 h[8];
        h[0] = __floats2half2_rn(a.x, a.y); h[1] = __floats2half2_rn(a.z, a.w);
        h[2] = __floats2half2_rn(b.x, b.y); h[3] = __floats2half2_rn(b.z, b.w);
        h[4] = __floats2half2_rn(c.x, c.y); h[5] = __floats2half2_rn(c.z, c.w);
        h[6] = __floats2half2_rn(d.x, d.y); h[7] = __floats2half2_rn(d.z, d.w);
        int off = k * 128 + n0 * 2;
        *(uint4*)&sW[SWZ(off)]      = *(uint4*)&h[0];
        *(uint4*)&sW[SWZ(off + 16)] = *(uint4*)&h[4];
    }
    __syncthreads();   // sc/sh ready (needed for BN at A-load)

    // A tile load (+BN+ReLU) -> fp16 smem (SW128). 2048 16B-chunks, 8 per thread.
#pragma unroll
    for (int i = 0; i < 8; i++) {
        int ch  = i * 256 + tid;
        int r   = ch >> 3;          // 0..255
        int c8  = ch & 7;           // 8-col chunk
        int n   = row0 + r;
        float v[8];
        if (n < N) {
            if (a_is_half) {
                uint4 u = ((const uint4*)Aptr)[n * 8 + c8];
                const __half2* hp = (const __half2*)&u;
#pragma unroll
                for (int j = 0; j < 4; j++) {
                    float2 f = __half22float2(hp[j]);
                    v[j * 2 + 0] = f.x;
                    v[j * 2 + 1] = f.y;
                }
            } else {
                float4 p = ((const float4*)Aptr)[n * 16 + c8 * 2];
                float4 q = ((const float4*)Aptr)[n * 16 + c8 * 2 + 1];
                v[0] = p.x; v[1] = p.y; v[2] = p.z; v[3] = p.w;
                v[4] = q.x; v[5] = q.y; v[6] = q.z; v[7] = q.w;
            }
        } else {
#pragma unroll
            for (int j = 0; j < 8; j++) v[j] = 0.f;
        }
        if (apply_bn) {
            int c0 = c8 * 8;
#pragma unroll
            for (int j = 0; j < 8; j++)
                v[j] = fmaxf(fmaf(v[j], sc[c0 + j], sh[c0 + j]), 0.f);
        }
        __half2 h[4];
#pragma unroll
        for (int j = 0; j < 4; j++) h[j] = __floats2half2_rn(v[j * 2], v[j * 2 + 1]);
        *(uint4*)&sA[SWZ(r * 128 + c8 * 16)] = *(uint4*)&h[0];
    }
    __syncthreads();

    // MMA mainloop
    int lane  = tid & 31;
    int warp  = tid >> 5;
    int rbase = warp * 32;

    float acc[2][8][4];
#pragma unroll
    for (int m = 0; m < 2; m++)
#pragma unroll
        for (int nt = 0; nt < 8; nt++)
#pragma unroll
            for (int j = 0; j < 4; j++) acc[m][nt][j] = 0.f;

    uint32_t sA_u = s2u(sA);
    uint32_t sW_u = s2u(sW);
    int lr  = lane & 15;        // row / k within 16
    int lhi = lane >> 4;        // 16B sub-block select

#pragma unroll
    for (int ks = 0; ks < 4; ks++) {
        uint32_t a[2][4];
#pragma unroll
        for (int m = 0; m < 2; m++) {
            int off = (rbase + m * 16 + lr) * 128 + (ks * 16 + lhi * 8) * 2;
            ldm_x4(a[m][0], a[m][1], a[m][2], a[m][3], sA_u + SWZ(off));
        }
        uint32_t b[8][2];
#pragma unroll
        for (int np = 0; np < 4; np++) {
            int off = (ks * 16 + lr) * 128 + (np * 16 + lhi * 8) * 2;
            uint32_t r0, r1, r2, r3;
            ldm_x4t(r0, r1, r2, r3, sW_u + SWZ(off));
            b[np * 2 + 0][0] = r0; b[np * 2 + 0][1] = r1;
            b[np * 2 + 1][0] = r2; b[np * 2 + 1][1] = r3;
        }
#pragma unroll
        for (int m = 0; m < 2; m++)
#pragma unroll
            for (int nt = 0; nt < 8; nt++)
                mma16816(acc[m][nt], a[m], b[nt]);
    }

    // epilogue: scale by dinv, fp16 store
    int q = lane >> 2;          // row group 0..7
    int c = lane & 3;           // col pair 0..3
#pragma unroll
    for (int m = 0; m < 2; m++) {
        int lr0 = rbase + m * 16 + q;
        int r0  = row0 + lr0;
        int r1  = r0 + 8;
        float d0 = sdinv[lr0];
        float d1 = sdinv[lr0 + 8];
#pragma unroll
        for (int nt = 0; nt < 8; nt++) {
            int ci = nt * 4 + c;   // half2 index within row
            if (r0 < N)
                ((__half2*)g_tsch)[r0 * 32 + ci] =
                    __floats2half2_rn(acc[m][nt][0] * d0, acc[m][nt][1] * d0);
            if (r1 < N)
                ((__half2*)g_tsch)[r1 * 32 + ci] =
                    __floats2half2_rn(acc[m][nt][2] * d1, acc[m][nt][3] * d1);
        }
    }
}

// ---------------- CSR gather-aggregate (fp16 msgs) + fused BN stats ----------------
// warp per node; lane holds feature pair (2*lane, 2*lane+1); fp32 accumulation.
__global__ void __launch_bounds__(256) k_gather(int layer, int N)
{
    __shared__ float ssum[64], ssq[64];
    int tid  = threadIdx.x;
    int lane = tid & 31;
    int wid  = tid >> 5;
    if (tid < 64) { ssum[tid] = 0.f; ssq[tid] = 0.f; }
    __syncthreads();

    float2 lsum = make_float2(0.f, 0.f);
    float2 lsq  = make_float2(0.f, 0.f);

    const __half2* base = (const __half2*)g_tsch;
    int warps = gridDim.x * 8;
    for (int n = blockIdx.x * 8 + wid; n < N; n += warps) {
        int s0 = g_rowptr[n];
        int s1 = g_rowptr[n + 1];
        float2 acc = __half22float2(__ldg(&base[n * 32 + lane]));   // self loop
        int e = s0;
        for (; e + 8 <= s1; e += 8) {
            int i0 = g_csrc[e + 0];
            int i1 = g_csrc[e + 1];
            int i2 = g_csrc[e + 2];
            int i3 = g_csrc[e + 3];
            int i4 = g_csrc[e + 4];
            int i5 = g_csrc[e + 5];
            int i6 = g_csrc[e + 6];
            int i7 = g_csrc[e + 7];
            float2 v0 = __half22float2(__ldg(&base[i0 * 32 + lane]));
            float2 v1 = __half22float2(__ldg(&base[i1 * 32 + lane]));
            float2 v2 = __half22float2(__ldg(&base[i2 * 32 + lane]));
            float2 v3 = __half22float2(__ldg(&base[i3 * 32 + lane]));
            float2 v4 = __half22float2(__ldg(&base[i4 * 32 + lane]));
            float2 v5 = __half22float2(__ldg(&base[i5 * 32 + lane]));
            float2 v6 = __half22float2(__ldg(&base[i6 * 32 + lane]));
            float2 v7 = __half22float2(__ldg(&base[i7 * 32 + lane]));
            acc.x += ((v0.x + v1.x) + (v2.x + v3.x)) + ((v4.x + v5.x) + (v6.x + v7.x));
            acc.y += ((v0.y + v1.y) + (v2.y + v3.y)) + ((v4.y + v5.y) + (v6.y + v7.y));
        }
        for (; e + 4 <= s1; e += 4) {
            int i0 = g_csrc[e + 0];
            int i1 = g_csrc[e + 1];
            int i2 = g_csrc[e + 2];
            int i3 = g_csrc[e + 3];
            float2 v0 = __half22float2(__ldg(&base[i0 * 32 + lane]));
            float2 v1 = __half22float2(__ldg(&base[i1 * 32 + lane]));
            float2 v2 = __half22float2(__ldg(&base[i2 * 32 + lane]));
            float2 v3 = __half22float2(__ldg(&base[i3 * 32 + lane]));
            acc.x += (v0.x + v1.x) + (v2.x + v3.x);
            acc.y += (v0.y + v1.y) + (v2.y + v3.y);
        }
        for (; e < s1; ++e) {
            float2 v = __half22float2(__ldg(&base[g_csrc[e] * 32 + lane]));
            acc.x += v.x; acc.y += v.y;
        }
        float dv = g_dinv[n];
        float2 yv = make_float2(acc.x * dv, acc.y * dv);
        ((__half2*)g_yh)[n * 32 + lane] = __floats2half2_rn(yv.x, yv.y);
        lsum.x += yv.x; lsum.y += yv.y;
        lsq.x  += yv.x * yv.x; lsq.y += yv.y * yv.y;
    }

    atomicAdd(&ssum[lane * 2 + 0], lsum.x);
    atomicAdd(&ssum[lane * 2 + 1], lsum.y);
    atomicAdd(&ssq[lane * 2 + 0], lsq.x);
    atomicAdd(&ssq[lane * 2 + 1], lsq.y);
    __syncthreads();
    if (tid < 64) {
        atomicAdd(&g_stats[layer * 128 + tid], ssum[tid]);
        atomicAdd(&g_stats[layer * 128 + 64 + tid], ssq[tid]);
    }
}

// ---------------- pooling: BN+ReLU fused, run-length segment-sum (batch sorted) ----
#define PCHUNK 32
__global__ void __launch_bounds__(256) k_pool(const int* __restrict__ batch,
                                              const float* __restrict__ gammas,
                                              const float* __restrict__ betas,
                                              int layer, int N)
{
    int lane = threadIdx.x & 31;
    int warp = (blockIdx.x * blockDim.x + threadIdx.x) >> 5;
    int n0 = warp * PCHUNK;
    if (n0 >= N) return;
    int n1 = min(n0 + PCHUNK, N);

    float invN = 1.0f / (float)N;
    int c0 = lane * 2, c1 = c0 + 1;
    float m0 = g_stats[layer * 128 + c0] * invN;
    float m1 = g_stats[layer * 128 + c1] * invN;
    float v0 = g_stats[layer * 128 + 64 + c0] * invN - m0 * m0;
    float v1 = g_stats[layer * 128 + 64 + c1] * invN - m1 * m1;
    float s0 = gammas[layer * 64 + c0] * rsqrtf(v0 + BN_EPS);
    float s1 = gammas[layer * 64 + c1] * rsqrtf(v1 + BN_EPS);
    float h0 = betas[layer * 64 + c0] - m0 * s0;
    float h1 = betas[layer * 64 + c1] - m1 * s1;

    const __half2* y = (const __half2*)g_yh;
    int    cur = batch[n0];
    float2 acc = make_float2(0.f, 0.f);
    int    cnt = 0;
    for (int n = n0; n < n1; n++) {
        int g = batch[n];
        if (g != cur) {
            atomicAdd(&g_psum[cur * 64 + c0], acc.x);
            atomicAdd(&g_psum[cur * 64 + c1], acc.y);
            if (lane == 0) atomicAdd(&g_pcnt[cur], cnt);
            acc = make_float2(0.f, 0.f); cnt = 0; cur = g;
        }
        float2 t = __half22float2(y[n * 32 + lane]);
        t.x = fmaxf(fmaf(t.x, s0, h0), 0.f);
        t.y = fmaxf(fmaf(t.y, s1, h1), 0.f);
        acc.x += t.x; acc.y += t.y; cnt++;
    }
    atomicAdd(&g_psum[cur * 64 + c0], acc.x);
    atomicAdd(&g_psum[cur * 64 + c1], acc.y);
    if (lane == 0) atomicAdd(&g_pcnt[cur], cnt);
}

__global__ void k_div(int G, float* __restrict__ out)
{
    int t = blockIdx.x * blockDim.x + threadIdx.x;
    if (t < G * 64) {
        float c = (float)g_pcnt[t >> 6];
        out[t] = g_psum[t] / fmaxf(c, 1.0f);
    }
}

// ---------------- launch ----------------
extern "C" void kernel_launch(void* const* d_in, const int* in_sizes, int n_in,
                              void* d_out, int out_size)
{
    const float* x      = (const float*)d_in[0];
    const int*   ei     = (const int*)d_in[1];     // int32 (JAX x64 disabled)
    const int*   batch  = (const int*)d_in[2];     // int32
    const float* Ws     = (const float*)d_in[3];
    // d_in[4] = bs: cancels exactly through BatchNorm (uniform shift), skipped.
    const float* gammas = (const float*)d_in[5];
    const float* betas  = (const float*)d_in[6];

    int N = in_sizes[0] / 64;
    int E = in_sizes[1] / 2;
    int G = out_size / 64;

    void* p_yh;
    cudaGetSymbolAddress(&p_yh, g_yh);

    const int tb = 256;
    int E4 = E >> 2;

    k_zero<<<(N + tb - 1) / tb, tb>>>(N);
    k_degree<<<(max(E4, 1) + tb - 1) / tb, tb>>>(ei, E);

    int nb = (N + 1023) / 1024;   // <= 98 blocks: wave-1 co-resident
    k_scanall<<<nb, 1024>>>(N, E);
    k_fill<<<(max(E4, 1) + tb - 1) / tb, tb>>>(ei, E);

    for (int l = 0; l < NLAYERS; ++l) {
        const void* A = (l == 0) ? (const void*)x : (const void*)p_yh;
        k_mm<<<(N + 255) / 256, 256>>>(A, Ws + (size_t)l * 64 * 64,
                                       gammas, betas, l, N,
                                       (l > 0) ? 1 : 0, (l > 0) ? 1 : 0);
        k_gather<<<1184, 256>>>(l, N);
    }

    int pwarps  = (N + PCHUNK - 1) / PCHUNK;
    int pblocks = (pwarps + 7) / 8;
    k_pool<<<pblocks, 256>>>(batch, gammas, betas, NLAYERS - 1, N);
    k_div<<<(G * 64 + tb - 1) / tb, tb>>>(G, (float*)d_out);
}